// round 1
// baseline (speedup 1.0000x reference)
#include <cuda_runtime.h>

#define BB 8
#define SS 1024
#define DD 512
#define HH 8
#define DK 64

// Scratch (allocation-free: __device__ globals)
__device__ float g_qh[BB * SS * DD];    // [b*S+s][h*64+e]
__device__ float g_kh[BB * SS * DD];    // [b*S+s][h*64+e]
__device__ float g_vs[BB * SS * DK];    // [b*S+s][e]
__device__ float g_head[BB * SS * DK];  // [b*S+s][e]  (mean over heads)

// ---------------------------------------------------------------------------
// GEMM: C[m][n] = sum_k A[m][k] * W[n][k]    (A: MxK row-major, W: NxK row-major)
// block tile 64x64, k-tile 32, 256 threads, 4x4 register tile per thread
// ---------------------------------------------------------------------------
__global__ void gemm_awt_kernel(const float* __restrict__ A,
                                const float* __restrict__ W,
                                float* __restrict__ C,
                                int N, int K) {
    __shared__ float As[32][65];   // [kk][m], pad 65 -> conflict-free transpose write
    __shared__ float Bs[32][68];   // [kk][n], pad 68 -> float4-aligned reads
    const int m0 = blockIdx.x * 64;
    const int n0 = blockIdx.y * 64;
    const int tid = threadIdx.x;
    const int ty = tid >> 4;       // 0..15 -> rows ty*4..
    const int tx = tid & 15;       // 0..15 -> cols tx*4..

    float acc[4][4] = {};

    for (int k0 = 0; k0 < K; k0 += 32) {
        #pragma unroll
        for (int idx = tid; idx < 64 * 32; idx += 256) {
            int mm = idx >> 5, kk = idx & 31;
            As[kk][mm] = A[(m0 + mm) * K + k0 + kk];
        }
        #pragma unroll
        for (int idx = tid; idx < 64 * 32; idx += 256) {
            int nn = idx >> 5, kk = idx & 31;
            Bs[kk][nn] = W[(n0 + nn) * K + k0 + kk];
        }
        __syncthreads();

        #pragma unroll 8
        for (int kk = 0; kk < 32; kk++) {
            float a0 = As[kk][ty * 4 + 0];
            float a1 = As[kk][ty * 4 + 1];
            float a2 = As[kk][ty * 4 + 2];
            float a3 = As[kk][ty * 4 + 3];
            float4 bv = *(const float4*)&Bs[kk][tx * 4];
            acc[0][0] += a0 * bv.x; acc[0][1] += a0 * bv.y; acc[0][2] += a0 * bv.z; acc[0][3] += a0 * bv.w;
            acc[1][0] += a1 * bv.x; acc[1][1] += a1 * bv.y; acc[1][2] += a1 * bv.z; acc[1][3] += a1 * bv.w;
            acc[2][0] += a2 * bv.x; acc[2][1] += a2 * bv.y; acc[2][2] += a2 * bv.z; acc[2][3] += a2 * bv.w;
            acc[3][0] += a3 * bv.x; acc[3][1] += a3 * bv.y; acc[3][2] += a3 * bv.z; acc[3][3] += a3 * bv.w;
        }
        __syncthreads();
    }

    #pragma unroll
    for (int i = 0; i < 4; i++) {
        float4 ov = make_float4(acc[i][0], acc[i][1], acc[i][2], acc[i][3]);
        *(float4*)&C[(size_t)(m0 + ty * 4 + i) * N + n0 + tx * 4] = ov;
    }
}

// ---------------------------------------------------------------------------
// Attention: one block per (b, q-tile of 32 rows). Loops heads; scores tile in
// shared (32x1024), softmax, writes attn to gmem, accumulates PV in registers
// across heads, writes head-mean to g_head.
// ---------------------------------------------------------------------------
#define SC_STRIDE 1024
#define KT_PAD 132
// smem floats: sc 32*1024 | kt (union Ks_t[64][132] / Vs[128][64]) 8448 | qs 32*64
#define SMEM_ATTN_FLOATS (32 * 1024 + 64 * KT_PAD + 32 * 64)

__global__ void attn_kernel(float* __restrict__ out_attn) {
    extern __shared__ float smem[];
    float* sc   = smem;                       // [32][1024]
    float* kt_s = smem + 32 * 1024;           // Ks_t [e][c] pad 132 / Vs [kk][64]
    float* qs   = kt_s + 64 * KT_PAD;         // [32][64]

    const int b  = blockIdx.y;
    const int s0 = blockIdx.x * 32;
    const int tid = threadIdx.x;
    const int lane = tid & 31;
    const int warp = tid >> 5;

    // score mapping: rows warp*4.., cols lane*4..
    const int r0 = warp * 4;
    const int c0 = lane * 4;
    // O mapping: 16x16 thread grid, 2 rows x 4 cols each
    const int or0 = (tid >> 4) * 2;
    const int oc0 = (tid & 15) * 4;

    float oacc[2][4] = {};

    for (int h = 0; h < HH; h++) {
        // ---- load Q tile (32 x 64) ----
        #pragma unroll
        for (int idx = tid; idx < 32 * 64; idx += 256) {
            int r = idx >> 6, e = idx & 63;
            qs[r * 64 + e] = g_qh[(size_t)(b * SS + s0 + r) * DD + h * 64 + e];
        }

        // ---- scores: sc[r][c] = 0.125 * sum_e q[r][e] * k[c][e] ----
        for (int kt = 0; kt < 8; kt++) {
            __syncthreads();  // kt_s reuse + (kt==0) qs ready for all
            #pragma unroll
            for (int idx = tid; idx < 128 * 64; idx += 256) {
                int c = idx >> 6, e = idx & 63;
                kt_s[e * KT_PAD + c] = g_kh[(size_t)(b * SS + kt * 128 + c) * DD + h * 64 + e];
            }
            __syncthreads();

            float racc[4][4] = {};
            #pragma unroll 16
            for (int kk = 0; kk < 64; kk++) {
                float4 bv = *(const float4*)&kt_s[kk * KT_PAD + c0];
                float a0 = qs[(r0 + 0) * 64 + kk];
                float a1 = qs[(r0 + 1) * 64 + kk];
                float a2 = qs[(r0 + 2) * 64 + kk];
                float a3 = qs[(r0 + 3) * 64 + kk];
                racc[0][0] += a0 * bv.x; racc[0][1] += a0 * bv.y; racc[0][2] += a0 * bv.z; racc[0][3] += a0 * bv.w;
                racc[1][0] += a1 * bv.x; racc[1][1] += a1 * bv.y; racc[1][2] += a1 * bv.z; racc[1][3] += a1 * bv.w;
                racc[2][0] += a2 * bv.x; racc[2][1] += a2 * bv.y; racc[2][2] += a2 * bv.z; racc[2][3] += a2 * bv.w;
                racc[3][0] += a3 * bv.x; racc[3][1] += a3 * bv.y; racc[3][2] += a3 * bv.z; racc[3][3] += a3 * bv.w;
            }
            #pragma unroll
            for (int i = 0; i < 4; i++) {
                float4 sv = make_float4(racc[i][0] * 0.125f, racc[i][1] * 0.125f,
                                        racc[i][2] * 0.125f, racc[i][3] * 0.125f);
                *(float4*)&sc[(r0 + i) * SC_STRIDE + kt * 128 + c0] = sv;
            }
        }
        // each warp softmaxes exactly the rows it wrote -> no sync needed here

        // ---- softmax per row + write attn ----
        #pragma unroll
        for (int rr = 0; rr < 4; rr++) {
            int r = warp * 4 + rr;
            float* srow = &sc[r * SC_STRIDE];
            float m = -1e30f;
            for (int c = lane; c < SS; c += 32) m = fmaxf(m, srow[c]);
            #pragma unroll
            for (int o = 16; o > 0; o >>= 1) m = fmaxf(m, __shfl_xor_sync(0xffffffffu, m, o));
            float sum = 0.f;
            for (int c = lane; c < SS; c += 32) {
                float e = __expf(srow[c] - m);
                srow[c] = e;
                sum += e;
            }
            #pragma unroll
            for (int o = 16; o > 0; o >>= 1) sum += __shfl_xor_sync(0xffffffffu, sum, o);
            float inv = 1.0f / sum;
            float* arow = out_attn + (((size_t)(h * BB + b) * SS + s0 + r) * SS);
            for (int c = lane; c < SS; c += 32) {
                float p = srow[c] * inv;
                srow[c] = p;
                arow[c] = p;
            }
        }

        // ---- O += P @ vs  (registers persist across heads) ----
        for (int kt = 0; kt < 8; kt++) {
            __syncthreads();  // all softmax done (kt==0) + kt_s reuse
            #pragma unroll
            for (int idx = tid; idx < 128 * 64; idx += 256) {
                int kk = idx >> 6, e = idx & 63;
                kt_s[kk * 64 + e] = g_vs[(size_t)(b * SS + kt * 128 + kk) * DK + e];
            }
            __syncthreads();

            const float* p0row = &sc[or0 * SC_STRIDE + kt * 128];
            const float* p1row = &sc[(or0 + 1) * SC_STRIDE + kt * 128];
            #pragma unroll 8
            for (int kk = 0; kk < 128; kk++) {
                float p0 = p0row[kk];
                float p1 = p1row[kk];
                float4 vv = *(const float4*)&kt_s[kk * 64 + oc0];
                oacc[0][0] += p0 * vv.x; oacc[0][1] += p0 * vv.y; oacc[0][2] += p0 * vv.z; oacc[0][3] += p0 * vv.w;
                oacc[1][0] += p1 * vv.x; oacc[1][1] += p1 * vv.y; oacc[1][2] += p1 * vv.z; oacc[1][3] += p1 * vv.w;
            }
        }
        __syncthreads();  // before next head overwrites qs/sc
    }

    const float invH = 1.0f / HH;
    #pragma unroll
    for (int i = 0; i < 2; i++) {
        float4 ov = make_float4(oacc[i][0] * invH, oacc[i][1] * invH,
                                oacc[i][2] * invH, oacc[i][3] * invH);
        *(float4*)&g_head[(size_t)(b * SS + s0 + or0 + i) * DK + oc0] = ov;
    }
}

// ---------------------------------------------------------------------------
extern "C" void kernel_launch(void* const* d_in, const int* in_sizes, int n_in,
                              void* d_out, int out_size) {
    const float* q  = (const float*)d_in[0];
    const float* k  = (const float*)d_in[1];
    const float* v  = (const float*)d_in[2];
    const float* Wq = (const float*)d_in[3];  // [H*64][512]
    const float* Wk = (const float*)d_in[4];  // [H*64][512]
    const float* Wv = (const float*)d_in[5];  // [64][512]
    const float* Wo = (const float*)d_in[6];  // [512][64]
    float* out  = (float*)d_out;                       // [B,S,D]
    float* attn = out + (size_t)BB * SS * DD;          // [H,B,S,S]

    float *p_qh, *p_kh, *p_vs, *p_head;
    cudaGetSymbolAddress((void**)&p_qh, g_qh);
    cudaGetSymbolAddress((void**)&p_kh, g_kh);
    cudaGetSymbolAddress((void**)&p_vs, g_vs);
    cudaGetSymbolAddress((void**)&p_head, g_head);

    cudaFuncSetAttribute(attn_kernel, cudaFuncAttributeMaxDynamicSharedMemorySize,
                         SMEM_ATTN_FLOATS * sizeof(float));

    const int M = BB * SS;  // 8192

    // projections
    gemm_awt_kernel<<<dim3(M / 64, DD / 64), 256>>>(q, Wq, p_qh, DD, DD);
    gemm_awt_kernel<<<dim3(M / 64, DD / 64), 256>>>(k, Wk, p_kh, DD, DD);
    gemm_awt_kernel<<<dim3(M / 64, DK / 64), 256>>>(v, Wv, p_vs, DK, DD);

    // attention + attn output + head mean
    attn_kernel<<<dim3(SS / 32, BB), 256, SMEM_ATTN_FLOATS * sizeof(float)>>>(attn);

    // out = head_mean @ Wo^T
    gemm_awt_kernel<<<dim3(M / 64, DD / 64), 256>>>(p_head, Wo, out, DD, DK);
}

// round 6
// speedup vs baseline: 1.8641x; 1.8641x over previous
#include <cuda_runtime.h>
#include <cstdint>

#define BB 8
#define SS 1024
#define DD 512
#define HH 8
#define DK 64

// ---------------- scratch (__device__ globals; no allocs) ----------------
__device__ float g_qh[BB * SS * DD];          // [m][h*64+e]
__device__ float g_kh[BB * SS * DD];          // [m][h*64+e]
__device__ float g_vs[BB * SS * DK];          // [m][e]
__device__ float g_heads[HH * BB * SS * DK];  // [h][m][e]
__device__ float g_head[BB * SS * DK];        // [m][e]

// ---------------- helpers ----------------
__device__ __forceinline__ float rna_tf32(float x) {
    uint32_t u;
    asm("cvt.rna.tf32.f32 %0, %1;" : "=r"(u) : "f"(x));
    return __uint_as_float(u);
}

// mma.sync m16n8k8 tf32 (portable PTX, works at target sm_103)
__device__ __forceinline__ void mma8(float* c, const uint4& a, const uint2& b) {
    asm volatile(
        "mma.sync.aligned.m16n8k8.row.col.f32.tf32.tf32.f32 "
        "{%0,%1,%2,%3}, {%4,%5,%6,%7}, {%8,%9}, {%0,%1,%2,%3};"
        : "+f"(c[0]), "+f"(c[1]), "+f"(c[2]), "+f"(c[3])
        : "r"(a.x), "r"(a.y), "r"(a.z), "r"(a.w), "r"(b.x), "r"(b.y));
}

// ---- fragment-permuted smem layouts (conflict-free LDS.128 / LDS.64) ----
// A-operand tile layout: idx = ((row/16)*KS + col/8)*128 + t*4 + slot
//   t = (row%8)*4 + (col%4), slot = (row%16>=8) + 2*(col%8>=4)
// stage 4 consecutive cols (col % 4 == 0) of one row:
__device__ __forceinline__ void stageA(float* base, int KS, int r, int c, float4 v) {
    int idx = (((r >> 4) * KS + (c >> 3)) << 7) + ((r & 7) << 4) +
              (((r & 15) >= 8) ? 1 : 0) + (((c & 7) >= 4) ? 2 : 0);
    base[idx]      = rna_tf32(v.x);
    base[idx + 4]  = rna_tf32(v.y);
    base[idx + 8]  = rna_tf32(v.z);
    base[idx + 12] = rna_tf32(v.w);
}
// single-element A-store (arbitrary col)
__device__ __forceinline__ void stA1(float* base, int KS, int r, int c, float p) {
    int idx = (((r >> 4) * KS + (c >> 3)) << 7) + (((r & 7) << 2) + (c & 3)) * 4 +
              (((r & 15) >= 8) ? 1 : 0) + (((c & 7) >= 4) ? 2 : 0);
    base[idx] = rna_tf32(p);
}
// B-operand tile layout (col-major use): idx = ((n/8)*KS + k/8)*64 + t*2 + slot
//   t = (n%8)*4 + (k%4), slot = (k%8>=4)
// stage 4 consecutive k (k % 4 == 0), same n:
__device__ __forceinline__ void stageB(float* base, int KS, int n, int k, float4 v) {
    int idx = (((n >> 3) * KS + (k >> 3)) << 6) + ((n & 7) << 3) +
              (((k & 7) >= 4) ? 1 : 0);
    base[idx]     = rna_tf32(v.x);
    base[idx + 2] = rna_tf32(v.y);
    base[idx + 4] = rna_tf32(v.z);
    base[idx + 6] = rna_tf32(v.w);
}
// stage 4 consecutive n (n % 4 == 0), same k:
__device__ __forceinline__ void stageBn(float* base, int KS, int n, int k, float4 v) {
    int idx = (((n >> 3) * KS + (k >> 3)) << 6) + ((n & 7) << 3) + ((k & 3) << 1) +
              (((k & 7) >= 4) ? 1 : 0);
    base[idx]      = rna_tf32(v.x);
    base[idx + 8]  = rna_tf32(v.y);
    base[idx + 16] = rna_tf32(v.z);
    base[idx + 24] = rna_tf32(v.w);
}

// ===========================================================================
// Projection GEMM: C[m][n] = sum_k A[m][k] * W[n][k]
// block 128M x 64N, k-tile 32, 256 threads, warps 4M x 2N (warp tile 32x32)
// ===========================================================================
__global__ void gemm_tc(const float* __restrict__ A, const float* __restrict__ W,
                        float* __restrict__ C, int Ntot, int K) {
    __shared__ float Aa[4096];  // mt8 x ks4 x 128
    __shared__ float Bb[2048];  // nt8 x ks4 x 64
    const int tid = threadIdx.x, lane = tid & 31, warp = tid >> 5;
    const int warpM = warp & 3, warpN = warp >> 2;
    const int m0 = blockIdx.x * 128, n0 = blockIdx.y * 64;

    float acc[2][4][4] = {};

    for (int k0 = 0; k0 < K; k0 += 32) {
        __syncthreads();
        {   // stage A: 128x32
            int r = tid >> 1;
            const float* ap = &A[(size_t)(m0 + r) * K + k0];
            #pragma unroll
            for (int j = 0; j < 4; j++) {
                int c = ((tid & 1) << 4) + (j << 2);
                stageA(Aa, 4, r, c, *(const float4*)&ap[c]);
            }
        }
        {   // stage B: 64x32
            int n = tid >> 2;
            const float* wp = &W[(size_t)(n0 + n) * K + k0];
            #pragma unroll
            for (int j = 0; j < 2; j++) {
                int c = ((tid & 3) << 3) + (j << 2);
                stageB(Bb, 4, n, c, *(const float4*)&wp[c]);
            }
        }
        __syncthreads();
        #pragma unroll
        for (int ks = 0; ks < 4; ks++) {
            uint4 a0 = *(const uint4*)&Aa[((((warpM << 1) + 0) * 4 + ks) << 7) + (lane << 2)];
            uint4 a1 = *(const uint4*)&Aa[((((warpM << 1) + 1) * 4 + ks) << 7) + (lane << 2)];
            #pragma unroll
            for (int nt = 0; nt < 4; nt++) {
                uint2 b = *(const uint2*)&Bb[((((warpN << 2) + nt) * 4 + ks) << 6) + (lane << 1)];
                mma8(acc[0][nt], a0, b);
                mma8(acc[1][nt], a1, b);
            }
        }
    }

    #pragma unroll
    for (int mt = 0; mt < 2; mt++) {
        int rr = m0 + warpM * 32 + mt * 16 + (lane >> 2);
        #pragma unroll
        for (int nt = 0; nt < 4; nt++) {
            int cc = n0 + warpN * 32 + nt * 8 + ((lane & 3) << 1);
            *(float2*)&C[(size_t)rr * Ntot + cc] = make_float2(acc[mt][nt][0], acc[mt][nt][1]);
            *(float2*)&C[(size_t)(rr + 8) * Ntot + cc] = make_float2(acc[mt][nt][2], acc[mt][nt][3]);
        }
    }
}

// ===========================================================================
// Attention: block = (64 q-rows, h, b). 256 threads, warps 4M x 2N.
// Score tile per chunk: 64 x 128 (warp tile 16x64). Two-pass streaming softmax.
// smem floats: Qa 4096 | KVb 8192 | Pa 8192 | rowbuf 128
// ===========================================================================
#define ATTN_SMEM_FLOATS (4096 + 8192 + 8192 + 128)

__global__ void attn_tc(float* __restrict__ attn) {
    extern __shared__ float sm[];
    float* Qa = sm;               // A-layout, KS=8   (64 x 64)
    float* KVb = sm + 4096;       // B-layout: K(KS=8, nt16) or V(KS=16, nt8)
    float* Pa = sm + 12288;       // A-layout, KS=16  (64 x 128)
    float* rowbuf = sm + 20480;   // [2][64]

    const int tid = threadIdx.x, lane = tid & 31, warp = tid >> 5;
    const int warpM = warp & 3, warpN = warp >> 2;
    const int s0 = blockIdx.x * 64, h = blockIdx.y, b = blockIdx.z;

    const float* qbase = g_qh + (size_t)(b * SS + s0) * DD + h * DK;

    // stage Q (64 x 64)
    {
        int r = tid >> 2;
        const float* qp = &qbase[(size_t)r * DD];
        #pragma unroll
        for (int j = 0; j < 4; j++) {
            int e = ((tid & 3) << 4) + (j << 2);
            stageA(Qa, 8, r, e, *(const float4*)&qp[e]);
        }
    }

    float rs0 = 0.f, rs1 = 0.f;
    float sacc[8][4];
    float oacc[4][4] = {};

    // -------- pass 1: rowsums of exp(s/8) --------
    for (int ck = 0; ck < 8; ck++) {
        __syncthreads();
        {   // stage K chunk (128 keys x 64 e), B-layout KS=8
            int key = tid >> 1;
            const float* kp = g_kh + (size_t)(b * SS + ck * 128 + key) * DD + h * DK;
            #pragma unroll
            for (int j = 0; j < 8; j++) {
                int e = ((tid & 1) << 5) + (j << 2);
                stageB(KVb, 8, key, e, *(const float4*)&kp[e]);
            }
        }
        __syncthreads();
        #pragma unroll
        for (int nt = 0; nt < 8; nt++)
            #pragma unroll
            for (int i = 0; i < 4; i++) sacc[nt][i] = 0.f;
        #pragma unroll
        for (int ks = 0; ks < 8; ks++) {
            uint4 a = *(const uint4*)&Qa[((warpM * 8 + ks) << 7) + (lane << 2)];
            #pragma unroll
            for (int nt = 0; nt < 8; nt++) {
                uint2 bf = *(const uint2*)&KVb[(((warpN * 8 + nt) * 8 + ks) << 6) + (lane << 1)];
                mma8(sacc[nt], a, bf);
            }
        }
        #pragma unroll
        for (int nt = 0; nt < 8; nt++) {
            rs0 += __expf(sacc[nt][0] * 0.125f) + __expf(sacc[nt][1] * 0.125f);
            rs1 += __expf(sacc[nt][2] * 0.125f) + __expf(sacc[nt][3] * 0.125f);
        }
    }
    // quad reduce (full row within this warp's 64-col half)
    rs0 += __shfl_xor_sync(0xffffffffu, rs0, 1);
    rs0 += __shfl_xor_sync(0xffffffffu, rs0, 2);
    rs1 += __shfl_xor_sync(0xffffffffu, rs1, 1);
    rs1 += __shfl_xor_sync(0xffffffffu, rs1, 2);
    __syncthreads();
    if ((lane & 3) == 0) {
        int r = warpM * 16 + (lane >> 2);
        rowbuf[warpN * 64 + r] = rs0;
        rowbuf[warpN * 64 + r + 8] = rs1;
    }
    __syncthreads();
    const int rloc = warpM * 16 + (lane >> 2);
    const float inv0 = 1.0f / (rowbuf[rloc] + rowbuf[64 + rloc]);
    const float inv1 = 1.0f / (rowbuf[rloc + 8] + rowbuf[64 + rloc + 8]);

    float* attn_base = attn + ((size_t)(h * BB + b) * SS + s0) * SS;

    // -------- pass 2: recompute S, normalize, store attn, O += P @ V --------
    for (int ck = 0; ck < 8; ck++) {
        __syncthreads();  // protect KVb (prev V) and Pa reuse
        {
            int key = tid >> 1;
            const float* kp = g_kh + (size_t)(b * SS + ck * 128 + key) * DD + h * DK;
            #pragma unroll
            for (int j = 0; j < 8; j++) {
                int e = ((tid & 1) << 5) + (j << 2);
                stageB(KVb, 8, key, e, *(const float4*)&kp[e]);
            }
        }
        __syncthreads();
        #pragma unroll
        for (int nt = 0; nt < 8; nt++)
            #pragma unroll
            for (int i = 0; i < 4; i++) sacc[nt][i] = 0.f;
        #pragma unroll
        for (int ks = 0; ks < 8; ks++) {
            uint4 a = *(const uint4*)&Qa[((warpM * 8 + ks) << 7) + (lane << 2)];
            #pragma unroll
            for (int nt = 0; nt < 8; nt++) {
                uint2 bf = *(const uint2*)&KVb[(((warpN * 8 + nt) * 8 + ks) << 6) + (lane << 1)];
                mma8(sacc[nt], a, bf);
            }
        }
        __syncthreads();  // all warps done reading K from KVb
        {   // stage V chunk (k=key 128, n=e 64) into KVb, B-layout KS=16
            int key = tid >> 1;
            const float* vp = g_vs + (size_t)(b * SS + ck * 128 + key) * DK;
            #pragma unroll
            for (int j = 0; j < 8; j++) {
                int e = ((tid & 1) << 5) + (j << 2);
                stageBn(KVb, 16, e, key, *(const float4*)&vp[e]);
            }
        }
        // normalize + direct attn store (8B/thread, quad -> full 32B sectors) + Pa
        {
            int rA = warpM * 16 + (lane >> 2);
            #pragma unroll
            for (int nt = 0; nt < 8; nt++) {
                int c = warpN * 64 + nt * 8 + ((lane & 3) << 1);
                float p0 = __expf(sacc[nt][0] * 0.125f) * inv0;
                float p1 = __expf(sacc[nt][1] * 0.125f) * inv0;
                float p2 = __expf(sacc[nt][2] * 0.125f) * inv1;
                float p3 = __expf(sacc[nt][3] * 0.125f) * inv1;
                *(float2*)&attn_base[(size_t)rA * SS + ck * 128 + c] = make_float2(p0, p1);
                *(float2*)&attn_base[(size_t)(rA + 8) * SS + ck * 128 + c] = make_float2(p2, p3);
                stA1(Pa, 16, rA, c, p0);
                stA1(Pa, 16, rA, c + 1, p1);
                stA1(Pa, 16, rA + 8, c, p2);
                stA1(Pa, 16, rA + 8, c + 1, p3);
            }
        }
        __syncthreads();  // V staged + Pa visible
        // O += P @ V : warp O tile 16 x 32
        #pragma unroll
        for (int ks = 0; ks < 16; ks++) {
            uint4 a = *(const uint4*)&Pa[((warpM * 16 + ks) << 7) + (lane << 2)];
            #pragma unroll
            for (int nt = 0; nt < 4; nt++) {
                uint2 bf = *(const uint2*)&KVb[(((warpN * 4 + nt) * 16 + ks) << 6) + (lane << 1)];
                mma8(oacc[nt], a, bf);
            }
        }
    }

    // O epilogue -> g_heads[h][m][e]
    {
        int m = b * SS + s0 + warpM * 16 + (lane >> 2);
        float* hb = g_heads + (size_t)h * (BB * SS) * DK;
        #pragma unroll
        for (int nt = 0; nt < 4; nt++) {
            int cc = warpN * 32 + nt * 8 + ((lane & 3) << 1);
            *(float2*)&hb[(size_t)m * DK + cc] = make_float2(oacc[nt][0], oacc[nt][1]);
            *(float2*)&hb[(size_t)(m + 8) * DK + cc] = make_float2(oacc[nt][2], oacc[nt][3]);
        }
    }
}

// ===========================================================================
// Mean over heads: g_head = 0.125 * sum_h g_heads[h]
// ===========================================================================
__global__ void mean_heads() {
    int i = blockIdx.x * blockDim.x + threadIdx.x;  // float4 index < 131072
    const float4* H4 = (const float4*)g_heads;
    float4 a = H4[i];
    #pragma unroll
    for (int h = 1; h < HH; h++) {
        float4 t = H4[(size_t)h * 131072 + i];
        a.x += t.x; a.y += t.y; a.z += t.z; a.w += t.w;
    }
    a.x *= 0.125f; a.y *= 0.125f; a.z *= 0.125f; a.w *= 0.125f;
    ((float4*)g_head)[i] = a;
}

// ===========================================================================
extern "C" void kernel_launch(void* const* d_in, const int* in_sizes, int n_in,
                              void* d_out, int out_size) {
    const float* q  = (const float*)d_in[0];
    const float* k  = (const float*)d_in[1];
    const float* v  = (const float*)d_in[2];
    const float* Wq = (const float*)d_in[3];  // [512][512]
    const float* Wk = (const float*)d_in[4];  // [512][512]
    const float* Wv = (const float*)d_in[5];  // [64][512]
    const float* Wo = (const float*)d_in[6];  // [512][64]
    float* out  = (float*)d_out;                   // [B,S,D]
    float* attn = out + (size_t)BB * SS * DD;      // [H,B,S,S]

    float *p_qh, *p_kh, *p_vs, *p_head;
    cudaGetSymbolAddress((void**)&p_qh, g_qh);
    cudaGetSymbolAddress((void**)&p_kh, g_kh);
    cudaGetSymbolAddress((void**)&p_vs, g_vs);
    cudaGetSymbolAddress((void**)&p_head, g_head);

    const int ATTN_SMEM = ATTN_SMEM_FLOATS * sizeof(float);  // 82432 B
    cudaFuncSetAttribute(attn_tc, cudaFuncAttributeMaxDynamicSharedMemorySize, ATTN_SMEM);

    // projections
    gemm_tc<<<dim3(64, 8), 256>>>(q, Wq, p_qh, DD, DD);
    gemm_tc<<<dim3(64, 8), 256>>>(k, Wk, p_kh, DD, DD);
    gemm_tc<<<dim3(64, 1), 256>>>(v, Wv, p_vs, DK, DD);

    // attention (attn output + per-head O)
    attn_tc<<<dim3(16, HH, BB), 256, ATTN_SMEM>>>(attn);

    // head mean + output projection
    mean_heads<<<512, 256>>>();
    gemm_tc<<<dim3(64, 8), 256>>>(p_head, Wo, out, DD, DK);
}

// round 7
// speedup vs baseline: 2.9670x; 1.5917x over previous
#include <cuda_runtime.h>
#include <cstdint>

#define BB 8
#define SS 1024
#define DD 512
#define HH 8
#define DK 64

// ---------------- scratch (__device__ globals; no allocs) ----------------
__device__ float g_qh[BB * SS * DD];          // [m][h*64+e]
__device__ float g_kh[BB * SS * DD];          // [m][h*64+e]
__device__ float g_vs[BB * SS * DK];          // [m][e]
__device__ float g_heads[HH * BB * SS * DK];  // [h][m][e]
__device__ float g_head[BB * SS * DK];        // [m][e]

// ---------------- helpers ----------------
__device__ __forceinline__ float rna_tf32(float x) {
    uint32_t u;
    asm("cvt.rna.tf32.f32 %0, %1;" : "=r"(u) : "f"(x));
    return __uint_as_float(u);
}
__device__ __forceinline__ uint32_t rna_u(float x) {
    uint32_t u;
    asm("cvt.rna.tf32.f32 %0, %1;" : "=r"(u) : "f"(x));
    return u;
}
__device__ __forceinline__ void mma8(float* c, uint32_t a0, uint32_t a1, uint32_t a2, uint32_t a3,
                                     uint32_t b0, uint32_t b1) {
    asm volatile(
        "mma.sync.aligned.m16n8k8.row.col.f32.tf32.tf32.f32 "
        "{%0,%1,%2,%3}, {%4,%5,%6,%7}, {%8,%9}, {%0,%1,%2,%3};"
        : "+f"(c[0]), "+f"(c[1]), "+f"(c[2]), "+f"(c[3])
        : "r"(a0), "r"(a1), "r"(a2), "r"(a3), "r"(b0), "r"(b1));
}
__device__ __forceinline__ void mma16bf(float* c, uint32_t a0, uint32_t a1, uint32_t a2, uint32_t a3,
                                        uint32_t b0, uint32_t b1) {
    asm volatile(
        "mma.sync.aligned.m16n8k16.row.col.f32.bf16.bf16.f32 "
        "{%0,%1,%2,%3}, {%4,%5,%6,%7}, {%8,%9}, {%0,%1,%2,%3};"
        : "+f"(c[0]), "+f"(c[1]), "+f"(c[2]), "+f"(c[3])
        : "r"(a0), "r"(a1), "r"(a2), "r"(a3), "r"(b0), "r"(b1));
}
__device__ __forceinline__ uint32_t packbf(float hi, float lo) {
    uint32_t r;
    asm("cvt.rn.bf16x2.f32 %0, %1, %2;" : "=r"(r) : "f"(hi), "f"(lo));
    return r;
}
__device__ __forceinline__ float blo(uint32_t u) { return __uint_as_float(u << 16); }
__device__ __forceinline__ float bhi(uint32_t u) { return __uint_as_float(u & 0xFFFF0000u); }

// ===========================================================================
// Projection GEMM: C[m][n] = sum_k A[m][k] * W[n][k]
// block 128M x BN, k-tile 32, 256 threads, warps 4M x 2N.
// smem: transposed, conflict-engineered: At[k][m] stride 136, Wt[k][n] stride BN+8.
// ===========================================================================
template <int BN>
__global__ void __launch_bounds__(256, 2) gemm_tc(const float* __restrict__ A,
                                                  const float* __restrict__ W,
                                                  float* __restrict__ C, int Ntot, int K) {
    __shared__ float At[32 * 136];
    __shared__ float Wt[32 * (BN + 8)];
    const int WS = BN + 8;
    const int NT = BN / 16;  // nt per warp (8 for BN=128, 4 for BN=64)
    const int tid = threadIdx.x, lane = tid & 31, warp = tid >> 5;
    const int warpM = warp & 3, warpN = warp >> 2;
    const int r4 = lane >> 2, c4 = lane & 3;
    const int m0 = blockIdx.x * 128, n0 = blockIdx.y * BN;

    float acc[2][BN / 16][4];
    #pragma unroll
    for (int mt = 0; mt < 2; mt++)
        #pragma unroll
        for (int nt = 0; nt < NT; nt++)
            #pragma unroll
            for (int i = 0; i < 4; i++) acc[mt][nt][i] = 0.f;

    for (int k0 = 0; k0 < K; k0 += 32) {
        __syncthreads();
        {   // stage At: m = tid&127, k-half = tid>>7
            int m = tid & 127, kh = (tid >> 7) * 16;
            const float* ap = &A[(size_t)(m0 + m) * K + k0 + kh];
            #pragma unroll
            for (int j = 0; j < 4; j++) {
                float4 v = *(const float4*)&ap[j * 4];
                int kb = kh + j * 4;
                At[(kb + 0) * 136 + m] = rna_tf32(v.x);
                At[(kb + 1) * 136 + m] = rna_tf32(v.y);
                At[(kb + 2) * 136 + m] = rna_tf32(v.z);
                At[(kb + 3) * 136 + m] = rna_tf32(v.w);
            }
        }
        if (BN == 128) {  // stage Wt 128x32
            int n = tid & 127, kh = (tid >> 7) * 16;
            const float* wp = &W[(size_t)(n0 + n) * K + k0 + kh];
            #pragma unroll
            for (int j = 0; j < 4; j++) {
                float4 v = *(const float4*)&wp[j * 4];
                int kb = kh + j * 4;
                Wt[(kb + 0) * WS + n] = rna_tf32(v.x);
                Wt[(kb + 1) * WS + n] = rna_tf32(v.y);
                Wt[(kb + 2) * WS + n] = rna_tf32(v.z);
                Wt[(kb + 3) * WS + n] = rna_tf32(v.w);
            }
        } else {  // BN==64: n = tid&63, k-quarter = tid>>6
            int n = tid & 63, kq = (tid >> 6) * 8;
            const float* wp = &W[(size_t)(n0 + n) * K + k0 + kq];
            #pragma unroll
            for (int j = 0; j < 2; j++) {
                float4 v = *(const float4*)&wp[j * 4];
                int kb = kq + j * 4;
                Wt[(kb + 0) * WS + n] = rna_tf32(v.x);
                Wt[(kb + 1) * WS + n] = rna_tf32(v.y);
                Wt[(kb + 2) * WS + n] = rna_tf32(v.z);
                Wt[(kb + 3) * WS + n] = rna_tf32(v.w);
            }
        }
        __syncthreads();
        #pragma unroll
        for (int ks = 0; ks < 4; ks++) {
            const int kk = ks * 8 + c4;
            uint32_t a[2][4];
            #pragma unroll
            for (int mt = 0; mt < 2; mt++) {
                int rr = warpM * 32 + mt * 16 + r4;
                a[mt][0] = __float_as_uint(At[kk * 136 + rr]);
                a[mt][1] = __float_as_uint(At[kk * 136 + rr + 8]);
                a[mt][2] = __float_as_uint(At[(kk + 4) * 136 + rr]);
                a[mt][3] = __float_as_uint(At[(kk + 4) * 136 + rr + 8]);
            }
            #pragma unroll
            for (int nt = 0; nt < NT; nt++) {
                int nn = warpN * (BN / 2) + nt * 8 + r4;
                uint32_t b0 = __float_as_uint(Wt[kk * WS + nn]);
                uint32_t b1 = __float_as_uint(Wt[(kk + 4) * WS + nn]);
                mma8(acc[0][nt], a[0][0], a[0][1], a[0][2], a[0][3], b0, b1);
                mma8(acc[1][nt], a[1][0], a[1][1], a[1][2], a[1][3], b0, b1);
            }
        }
    }

    #pragma unroll
    for (int mt = 0; mt < 2; mt++) {
        int rr = m0 + warpM * 32 + mt * 16 + r4;
        #pragma unroll
        for (int nt = 0; nt < NT; nt++) {
            int cc = n0 + warpN * (BN / 2) + nt * 8 + 2 * c4;
            *(float2*)&C[(size_t)rr * Ntot + cc] = make_float2(acc[mt][nt][0], acc[mt][nt][1]);
            *(float2*)&C[(size_t)(rr + 8) * Ntot + cc] = make_float2(acc[mt][nt][2], acc[mt][nt][3]);
        }
    }
}

// ===========================================================================
// Attention: block = (128 q-rows, h, b), 256 threads = 8 warps x 16 rows.
// Each warp owns full key range -> warp-local softmax & PV, no cross-warp sync.
// Q frags in registers. Score: tf32 mma. PV: bf16 hi/lo split mma, P frags
// built in-register from score C-frags (no smem round trip).
// smem: kt[64][136] f32 (34816B) | vh[64][68] u32 | vl[64][68] u32 (17408B ea)
// ===========================================================================
#define KTS 136
#define VTS 68
#define ATTN_SMEM (64 * KTS * 4 + 2 * 64 * VTS * 4)

__global__ void __launch_bounds__(256, 1) attn_tc(float* __restrict__ attn) {
    extern __shared__ float sm[];
    float* kt = sm;                                   // [e 64][key 128 +8]
    uint32_t* vh_s = (uint32_t*)(sm + 64 * KTS);      // [e 64][keypair 64 +4]
    uint32_t* vl_s = vh_s + 64 * VTS;

    const int tid = threadIdx.x, lane = tid & 31, warp = tid >> 5;
    const int r4 = lane >> 2, c4 = lane & 3;
    const int s0 = blockIdx.x * 128, h = blockIdx.y, b = blockIdx.z;
    const int row = s0 + warp * 16 + r4;  // this thread's q-row (and row+8)

    const float* qbase = g_qh + (size_t)(b * SS) * DD + h * DK;
    const float* kbase = g_kh + (size_t)(b * SS) * DD + h * DK;
    const float* vbase = g_vs + (size_t)(b * SS) * DK;

    // Q A-fragments: loaded once, live in registers for both passes
    uint32_t qa[8][4];
    #pragma unroll
    for (int ks = 0; ks < 8; ks++) {
        int cc = ks * 8 + c4;
        qa[ks][0] = rna_u(qbase[(size_t)row * DD + cc]);
        qa[ks][1] = rna_u(qbase[(size_t)(row + 8) * DD + cc]);
        qa[ks][2] = rna_u(qbase[(size_t)row * DD + cc + 4]);
        qa[ks][3] = rna_u(qbase[(size_t)(row + 8) * DD + cc + 4]);
    }

    float sacc[16][4];
    float oacc[8][4];
    #pragma unroll
    for (int nt = 0; nt < 8; nt++)
        #pragma unroll
        for (int i = 0; i < 4; i++) oacc[nt][i] = 0.f;

    float rs0 = 0.f, rs1 = 0.f;

    // ---------------- pass 1: rowsums of exp(s/8) ----------------
    for (int ck = 0; ck < 8; ck++) {
        __syncthreads();
        {   // stage K chunk transposed: kt[e][key]
            int key = tid >> 1;
            int e0 = (tid & 1) * 32;
            const float* kp = &kbase[(size_t)(ck * 128 + key) * DD + e0];
            #pragma unroll
            for (int j = 0; j < 8; j++) {
                float4 v = *(const float4*)&kp[j * 4];
                int e = e0 + j * 4;
                kt[(e + 0) * KTS + key] = rna_tf32(v.x);
                kt[(e + 1) * KTS + key] = rna_tf32(v.y);
                kt[(e + 2) * KTS + key] = rna_tf32(v.z);
                kt[(e + 3) * KTS + key] = rna_tf32(v.w);
            }
        }
        __syncthreads();
        #pragma unroll
        for (int nt = 0; nt < 16; nt++)
            #pragma unroll
            for (int i = 0; i < 4; i++) sacc[nt][i] = 0.f;
        #pragma unroll
        for (int ks = 0; ks < 8; ks++) {
            int kk = ks * 8 + c4;
            #pragma unroll
            for (int nt = 0; nt < 16; nt++) {
                int nn = nt * 8 + r4;
                uint32_t b0 = __float_as_uint(kt[kk * KTS + nn]);
                uint32_t b1 = __float_as_uint(kt[(kk + 4) * KTS + nn]);
                mma8(sacc[nt], qa[ks][0], qa[ks][1], qa[ks][2], qa[ks][3], b0, b1);
            }
        }
        #pragma unroll
        for (int nt = 0; nt < 16; nt++) {
            rs0 += __expf(sacc[nt][0] * 0.125f) + __expf(sacc[nt][1] * 0.125f);
            rs1 += __expf(sacc[nt][2] * 0.125f) + __expf(sacc[nt][3] * 0.125f);
        }
    }
    rs0 += __shfl_xor_sync(0xffffffffu, rs0, 1);
    rs0 += __shfl_xor_sync(0xffffffffu, rs0, 2);
    rs1 += __shfl_xor_sync(0xffffffffu, rs1, 1);
    rs1 += __shfl_xor_sync(0xffffffffu, rs1, 2);
    const float inv0 = 1.0f / rs0, inv1 = 1.0f / rs1;

    float* arow0 = attn + (((size_t)(h * BB + b) * SS) + row) * SS;
    float* arow1 = arow0 + 8 * SS;

    // ---------------- pass 2: recompute S, normalize+store, PV ----------------
    for (int ck = 0; ck < 8; ck++) {
        __syncthreads();
        {   // stage K
            int key = tid >> 1;
            int e0 = (tid & 1) * 32;
            const float* kp = &kbase[(size_t)(ck * 128 + key) * DD + e0];
            #pragma unroll
            for (int j = 0; j < 8; j++) {
                float4 v = *(const float4*)&kp[j * 4];
                int e = e0 + j * 4;
                kt[(e + 0) * KTS + key] = rna_tf32(v.x);
                kt[(e + 1) * KTS + key] = rna_tf32(v.y);
                kt[(e + 2) * KTS + key] = rna_tf32(v.z);
                kt[(e + 3) * KTS + key] = rna_tf32(v.w);
            }
        }
        {   // stage V as bf16 hi/lo key-pairs: vh/vl[e][kp]
            int kp2 = tid >> 2;
            const float* va_p = &vbase[(size_t)(ck * 128 + 2 * kp2) * DK];
            const float* vb_p = va_p + DK;
            #pragma unroll
            for (int j = 0; j < 4; j++) {
                int e0 = (tid & 3) * 4 + j * 16;
                float4 va = *(const float4*)&va_p[e0];
                float4 vb = *(const float4*)&vb_p[e0];
                float fa[4] = {va.x, va.y, va.z, va.w};
                float fb[4] = {vb.x, vb.y, vb.z, vb.w};
                #pragma unroll
                for (int i = 0; i < 4; i++) {
                    uint32_t uh = packbf(fb[i], fa[i]);
                    uint32_t ul = packbf(fb[i] - bhi(uh), fa[i] - blo(uh));
                    vh_s[(e0 + i) * VTS + kp2] = uh;
                    vl_s[(e0 + i) * VTS + kp2] = ul;
                }
            }
        }
        __syncthreads();
        #pragma unroll
        for (int nt = 0; nt < 16; nt++)
            #pragma unroll
            for (int i = 0; i < 4; i++) sacc[nt][i] = 0.f;
        #pragma unroll
        for (int ks = 0; ks < 8; ks++) {
            int kk = ks * 8 + c4;
            #pragma unroll
            for (int nt = 0; nt < 16; nt++) {
                int nn = nt * 8 + r4;
                uint32_t b0 = __float_as_uint(kt[kk * KTS + nn]);
                uint32_t b1 = __float_as_uint(kt[(kk + 4) * KTS + nn]);
                mma8(sacc[nt], qa[ks][0], qa[ks][1], qa[ks][2], qa[ks][3], b0, b1);
            }
        }
        // normalize + coalesced attn store (overwrite sacc with P)
        #pragma unroll
        for (int nt = 0; nt < 16; nt++) {
            float p0 = __expf(sacc[nt][0] * 0.125f) * inv0;
            float p1 = __expf(sacc[nt][1] * 0.125f) * inv0;
            float p2 = __expf(sacc[nt][2] * 0.125f) * inv1;
            float p3 = __expf(sacc[nt][3] * 0.125f) * inv1;
            sacc[nt][0] = p0; sacc[nt][1] = p1; sacc[nt][2] = p2; sacc[nt][3] = p3;
            *(float2*)&arow0[ck * 128 + nt * 8 + 2 * c4] = make_float2(p0, p1);
            *(float2*)&arow1[ck * 128 + nt * 8 + 2 * c4] = make_float2(p2, p3);
        }
        // PV: P C-frags -> bf16 hi/lo A-frags in-register, V from smem
        #pragma unroll
        for (int kk = 0; kk < 8; kk++) {
            const float* sa = sacc[2 * kk];
            const float* sb = sacc[2 * kk + 1];
            uint32_t ah0 = packbf(sa[1], sa[0]);
            uint32_t ah1 = packbf(sa[3], sa[2]);
            uint32_t ah2 = packbf(sb[1], sb[0]);
            uint32_t ah3 = packbf(sb[3], sb[2]);
            uint32_t al0 = packbf(sa[1] - bhi(ah0), sa[0] - blo(ah0));
            uint32_t al1 = packbf(sa[3] - bhi(ah1), sa[2] - blo(ah1));
            uint32_t al2 = packbf(sb[1] - bhi(ah2), sb[0] - blo(ah2));
            uint32_t al3 = packbf(sb[3] - bhi(ah3), sb[2] - blo(ah3));
            #pragma unroll
            for (int nt = 0; nt < 8; nt++) {
                int nn = nt * 8 + r4;
                int kb = kk * 8 + c4;
                uint32_t bh0 = vh_s[nn * VTS + kb];
                uint32_t bh1 = vh_s[nn * VTS + kb + 4];
                mma16bf(oacc[nt], ah0, ah1, ah2, ah3, bh0, bh1);
                mma16bf(oacc[nt], al0, al1, al2, al3, bh0, bh1);
                uint32_t bl0 = vl_s[nn * VTS + kb];
                uint32_t bl1 = vl_s[nn * VTS + kb + 4];
                mma16bf(oacc[nt], ah0, ah1, ah2, ah3, bl0, bl1);
            }
        }
    }

    // O epilogue -> g_heads[h][m][e]
    {
        float* hb = g_heads + (size_t)h * (BB * SS) * DK + (size_t)(b * SS + row) * DK;
        #pragma unroll
        for (int nt = 0; nt < 8; nt++) {
            int cc = nt * 8 + 2 * c4;
            *(float2*)&hb[cc] = make_float2(oacc[nt][0], oacc[nt][1]);
            *(float2*)&hb[8 * DK + cc] = make_float2(oacc[nt][2], oacc[nt][3]);
        }
    }
}

// ===========================================================================
// Mean over heads: g_head = 0.125 * sum_h g_heads[h]
// ===========================================================================
__global__ void mean_heads() {
    int i = blockIdx.x * blockDim.x + threadIdx.x;  // float4 index < 131072
    const float4* H4 = (const float4*)g_heads;
    float4 a = H4[i];
    #pragma unroll
    for (int h = 1; h < HH; h++) {
        float4 t = H4[(size_t)h * 131072 + i];
        a.x += t.x; a.y += t.y; a.z += t.z; a.w += t.w;
    }
    a.x *= 0.125f; a.y *= 0.125f; a.z *= 0.125f; a.w *= 0.125f;
    ((float4*)g_head)[i] = a;
}

// ===========================================================================
extern "C" void kernel_launch(void* const* d_in, const int* in_sizes, int n_in,
                              void* d_out, int out_size) {
    const float* q  = (const float*)d_in[0];
    const float* k  = (const float*)d_in[1];
    const float* v  = (const float*)d_in[2];
    const float* Wq = (const float*)d_in[3];  // [512][512]
    const float* Wk = (const float*)d_in[4];  // [512][512]
    const float* Wv = (const float*)d_in[5];  // [64][512]
    const float* Wo = (const float*)d_in[6];  // [512][64]
    float* out  = (float*)d_out;                   // [B,S,D]
    float* attn = out + (size_t)BB * SS * DD;      // [H,B,S,S]

    float *p_qh, *p_kh, *p_vs, *p_head;
    cudaGetSymbolAddress((void**)&p_qh, g_qh);
    cudaGetSymbolAddress((void**)&p_kh, g_kh);
    cudaGetSymbolAddress((void**)&p_vs, g_vs);
    cudaGetSymbolAddress((void**)&p_head, g_head);

    cudaFuncSetAttribute(attn_tc, cudaFuncAttributeMaxDynamicSharedMemorySize, ATTN_SMEM);

    // projections
    gemm_tc<128><<<dim3(64, 4), 256>>>(q, Wq, p_qh, DD, DD);
    gemm_tc<128><<<dim3(64, 4), 256>>>(k, Wk, p_kh, DD, DD);
    gemm_tc<64><<<dim3(64, 1), 256>>>(v, Wv, p_vs, DK, DD);

    // attention (attn output + per-head O)
    attn_tc<<<dim3(8, HH, BB), 256, ATTN_SMEM>>>(attn);

    // head mean + output projection
    mean_heads<<<512, 256>>>();
    gemm_tc<128><<<dim3(64, 4), 256>>>(p_head, Wo, out, DD, DK);
}